// round 2
// baseline (speedup 1.0000x reference)
#include <cuda_runtime.h>
#include <cuda_bf16.h>
#include <math.h>

#define NN 15828
#define BB 64
#define MAXE 300000
#define NBLK_MLP1 ((NN + 63) / 64)   // 248

// ---------------- scratch (device globals; no allocation) ----------------
__device__ int   g_dout[NN];
__device__ int   g_din[NN];
__device__ int   g_cursor[NN];
__device__ int   g_rs[NN + 1];
__device__ int   g_csr[MAXE];
__device__ float g_rsdo[NN];
__device__ float g_rsdi[NN];
__device__ float g_xs[NN * BB];
__device__ float g_s0[NN * BB];
__device__ float g_t [NN * BB];
__device__ float g_z [NN * BB];
__device__ float g_consts[4];        // Cpos, Cneg, max|b0|
__device__ float g_partial[NBLK_MLP1 * 100 * 64];
__device__ float g_y0[64 * 100];

__device__ __forceinline__ float leaky(float x) { return x > 0.f ? x : 0.01f * x; }

// ---------------- graph build ----------------
__global__ void k_init() {
    int i = blockIdx.x * blockDim.x + threadIdx.x;
    if (i < NN) { g_dout[i] = 0; g_din[i] = 0; g_cursor[i] = 0; }
}

__global__ void k_deg(const int* __restrict__ src, const int* __restrict__ dst, int E) {
    int e = blockIdx.x * blockDim.x + threadIdx.x;
    if (e < E) {
        atomicAdd(&g_dout[src[e]], 1);
        atomicAdd(&g_din [dst[e]], 1);
    }
}

__global__ void k_scan() {
    __shared__ int tile[1024];
    __shared__ int carry_s;
    int t = threadIdx.x;
    if (t == 0) carry_s = 0;
    __syncthreads();
    for (int base = 0; base < NN; base += 1024) {
        int i = base + t;
        int v = (i < NN) ? g_din[i] : 0;
        tile[t] = v;
        __syncthreads();
        #pragma unroll
        for (int off = 1; off < 1024; off <<= 1) {
            int add = (t >= off) ? tile[t - off] : 0;
            __syncthreads();
            tile[t] += add;
            __syncthreads();
        }
        int cbase = carry_s;
        if (i < NN) g_rs[i] = cbase + tile[t] - v;   // exclusive
        __syncthreads();
        if (t == 0) carry_s = cbase + tile[1023];
        __syncthreads();
    }
    if (t == 0) g_rs[NN] = carry_s;
}

__global__ void k_fill(const int* __restrict__ src, const int* __restrict__ dst, int E) {
    int e = blockIdx.x * blockDim.x + threadIdx.x;
    if (e < E) {
        int d = dst[e];
        int p = atomicAdd(&g_cursor[d], 1);
        g_csr[g_rs[d] + p] = src[e];
    }
}

__global__ void k_rsd() {
    int n = blockIdx.x * blockDim.x + threadIdx.x;
    if (n < NN) {
        g_rsdo[n] = rsqrtf(fmaxf((float)g_dout[n], 1.f));
        g_rsdi[n] = rsqrtf(fmaxf((float)g_din[n],  1.f));
    }
}

// ---------------- constants for the folded conv0->conv1 path ----------------
__global__ void k_consts(const float* __restrict__ W0, const float* __restrict__ b0,
                         const float* __restrict__ W1) {
    __shared__ float sp[128], sn[128], sb[128];
    int t = threadIdx.x;
    float cp = 0.f, cn = 0.f, bm = 0.f;
    if (t < 100) {
        float w0 = W0[t], w1 = W1[t], p = w0 * w1;
        cp = p * (w0 > 0.f ? 1.f : 0.01f);
        cn = p * (w0 < 0.f ? 1.f : 0.01f);
        bm = fabsf(b0[t]);
    }
    sp[t] = cp; sn[t] = cn; sb[t] = bm;
    __syncthreads();
    for (int o = 64; o; o >>= 1) {
        if (t < o) { sp[t] += sp[t + o]; sn[t] += sn[t + o]; sb[t] = fmaxf(sb[t], sb[t + o]); }
        __syncthreads();
    }
    if (t == 0) { g_consts[0] = sp[0]; g_consts[1] = sn[0]; g_consts[2] = sb[0]; }
}

// ---------------- pre-scale for conv0 ----------------
__global__ void k_xs(const float* __restrict__ in_feat) {
    int idx = blockIdx.x * blockDim.x + threadIdx.x;
    if (idx < NN * BB) g_xs[idx] = in_feat[idx] * g_rsdo[idx >> 6];
}

// ---------------- edge aggregation: one warp per dst node, float2/lane ----------------
// MODE 0: g_xs -> g_s0 (plain normalized sum)
// MODE 1: g_t  -> g_z  (sum, normalize, +b1, leaky)
// NOTE: arrays are resolved in DEVICE code — __device__ globals cannot be
// passed as host-side kernel arguments (that was the round-1 crash).
template <int MODE>
__global__ void k_agg(const float* __restrict__ b1) {
    const float2* __restrict__ x = (MODE == 0) ? (const float2*)g_xs : (const float2*)g_t;
    float2* __restrict__ out     = (MODE == 0) ? (float2*)g_s0       : (float2*)g_z;
    int node = blockIdx.x * (blockDim.x >> 5) + (threadIdx.x >> 5);
    if (node >= NN) return;
    int lane = threadIdx.x & 31;
    int beg = g_rs[node], end = g_rs[node + 1];
    float ax = 0.f, ay = 0.f;
    #pragma unroll 4
    for (int i = beg; i < end; i++) {
        int s = __ldg(&g_csr[i]);
        float2 v = x[s * 32 + lane];
        ax += v.x; ay += v.y;
    }
    float r = g_rsdi[node];
    float2 o;
    if (MODE == 0) {
        o.x = ax * r; o.y = ay * r;
    } else {
        float bb = b1[0];
        float vx = ax * r + bb, vy = ay * r + bb;
        o.x = leaky(vx); o.y = leaky(vy);
    }
    out[node * 32 + lane] = o;
}

// ---------------- folded conv0-activation + conv1 weight contraction ----------------
__global__ void k_t(const float* __restrict__ W0, const float* __restrict__ b0,
                    const float* __restrict__ W1) {
    int idx = blockIdx.x * blockDim.x + threadIdx.x;
    if (idx >= NN * BB) return;
    int n = idx >> 6;
    float s = g_s0[idx];
    float acc;
    if (g_consts[2] == 0.f) {                 // b0 == 0 fast path (true for this dataset)
        acc = s * (s > 0.f ? g_consts[0] : g_consts[1]);
    } else {                                   // exact general fallback
        acc = 0.f;
        #pragma unroll 4
        for (int f = 0; f < 100; f++) {
            float v = fmaf(s, __ldg(&W0[f]), __ldg(&b0[f]));
            acc = fmaf(leaky(v), __ldg(&W1[f]), acc);
        }
    }
    g_t[idx] = acc * g_rsdo[n];
}

// ---------------- MLP layer 1: [64 x 15828] @ [15828 x 100], split-N partials ----------------
__global__ void k_mlp1(const float* __restrict__ lw0) {
    __shared__ float ws[100 * 64];
    __shared__ float zs[64 * 64];
    int blk = blockIdx.x;
    int n0 = blk * 64;
    int tid = threadIdx.x;   // 256
    for (int idx = tid; idx < 100 * 64; idx += 256) {
        int j = idx >> 6, i = idx & 63;
        int n = n0 + i;
        ws[idx] = (n < NN) ? lw0[j * NN + n] : 0.f;
    }
    for (int idx = tid; idx < 64 * 64; idx += 256) {
        int i = idx >> 6, b = idx & 63;
        int n = n0 + i;
        zs[idx] = (n < NN) ? g_z[n * 64 + b] : 0.f;
    }
    __syncthreads();
    int b = tid & 63, jg = tid >> 6;
    int jb = jg * 25;
    float acc[25];
    #pragma unroll
    for (int jj = 0; jj < 25; jj++) acc[jj] = 0.f;
    for (int i = 0; i < 64; i += 4) {
        float z0 = zs[(i + 0) * 64 + b];
        float z1 = zs[(i + 1) * 64 + b];
        float z2 = zs[(i + 2) * 64 + b];
        float z3 = zs[(i + 3) * 64 + b];
        #pragma unroll
        for (int jj = 0; jj < 25; jj++) {
            const float4 w = *(const float4*)&ws[(jb + jj) * 64 + i];
            acc[jj] = fmaf(z0, w.x, acc[jj]);
            acc[jj] = fmaf(z1, w.y, acc[jj]);
            acc[jj] = fmaf(z2, w.z, acc[jj]);
            acc[jj] = fmaf(z3, w.w, acc[jj]);
        }
    }
    #pragma unroll
    for (int jj = 0; jj < 25; jj++)
        g_partial[blk * 6400 + (jb + jj) * 64 + b] = acc[jj];
}

__global__ void k_mlp1_reduce(const float* __restrict__ lb0) {
    int idx = blockIdx.x * blockDim.x + threadIdx.x;
    if (idx >= 6400) return;
    int j = idx >> 6, b = idx & 63;
    float s = 0.f;
    for (int k = 0; k < NBLK_MLP1; k++) s += g_partial[k * 6400 + idx];
    s += lb0[j];
    g_y0[b * 100 + j] = leaky(s);
}

// ---------------- MLP layers 2+3 ----------------
__global__ void k_tail(const float* __restrict__ lw2, const float* __restrict__ lb2,
                       const float* __restrict__ lw3, const float* __restrict__ lb3,
                       float* __restrict__ out) {
    __shared__ float y1s[64 * 100];
    int tid = threadIdx.x;   // 1024
    for (int idx = tid; idx < 6400; idx += 1024) {
        int b = idx / 100, k = idx % 100;
        float a = lb2[k];
        #pragma unroll 4
        for (int j = 0; j < 100; j++)
            a = fmaf(g_y0[b * 100 + j], lw2[k * 100 + j], a);
        y1s[b * 100 + k] = leaky(a);
    }
    __syncthreads();
    for (int idx = tid; idx < 640; idx += 1024) {
        int b = idx / 10, c = idx % 10;
        float a = lb3[c];
        #pragma unroll 4
        for (int k = 0; k < 100; k++)
            a = fmaf(y1s[b * 100 + k], lw3[c * 100 + k], a);
        out[idx] = leaky(a);
    }
}

// ---------------- launch ----------------
extern "C" void kernel_launch(void* const* d_in, const int* in_sizes, int n_in,
                              void* d_out, int out_size) {
    const float* in_feat = (const float*)d_in[0];
    const int*   ei      = (const int*)  d_in[1];
    const float* W0      = (const float*)d_in[2];
    const float* b0      = (const float*)d_in[3];
    const float* W1      = (const float*)d_in[4];
    const float* b1      = (const float*)d_in[5];
    const float* lw0     = (const float*)d_in[6];
    const float* lb0     = (const float*)d_in[7];
    const float* lw2     = (const float*)d_in[8];
    const float* lb2     = (const float*)d_in[9];
    const float* lw3     = (const float*)d_in[10];
    const float* lb3     = (const float*)d_in[11];
    float* out = (float*)d_out;

    int E = in_sizes[1] / 2;
    const int* src = ei;
    const int* dst = ei + E;

    int gN  = (NN + 255) / 256;
    int gE  = (E + 255) / 256;
    int gNB = (NN * BB + 255) / 256;
    int gAgg = (NN + 7) / 8;          // 8 warps (nodes) per 256-thread block

    k_init<<<gN, 256>>>();
    k_deg<<<gE, 256>>>(src, dst, E);
    k_scan<<<1, 1024>>>();
    k_fill<<<gE, 256>>>(src, dst, E);
    k_rsd<<<gN, 256>>>();
    k_consts<<<1, 128>>>(W0, b0, W1);
    k_xs<<<gNB, 256>>>(in_feat);
    k_agg<0><<<gAgg, 256>>>(b1);
    k_t<<<gNB, 256>>>(W0, b0, W1);
    k_agg<1><<<gAgg, 256>>>(b1);
    k_mlp1<<<NBLK_MLP1, 256>>>(lw0);
    k_mlp1_reduce<<<(6400 + 255) / 256, 256>>>(lb0);
    k_tail<<<1, 1024>>>(lw2, lb2, lw3, lb3, out);
}

// round 4
// speedup vs baseline: 2.7398x; 2.7398x over previous
#include <cuda_runtime.h>
#include <cuda_bf16.h>
#include <math.h>

#define NN 15828
#define BB 64
#define MAXE 300000
#define NBLK_MLP1 ((NN + 63) / 64)   // 248

// ---------------- scratch (device globals; no allocation) ----------------
__device__ int   g_dout[NN];
__device__ int   g_din[NN];
__device__ int   g_cursor[NN];
__device__ int   g_rs[NN + 1];
__device__ int   g_csr[MAXE];
__device__ float g_rsdo[NN];
__device__ float g_rsdi[NN];
__device__ float g_t [NN * BB];
__device__ float g_z [NN * BB];
__device__ float g_consts[4];        // Cpos, Cneg, max|b0|
__device__ float g_partial[NBLK_MLP1 * 100 * 64];
__device__ float g_y0[64 * 100];     // [b*100 + j]
__device__ float g_y1[100 * 64];     // [k*64 + b]

__device__ __forceinline__ float leaky(float x) { return x > 0.f ? x : 0.01f * x; }

// ---------------- graph build ----------------
__global__ void k_init() {
    int i = blockIdx.x * blockDim.x + threadIdx.x;
    if (i < NN) { g_dout[i] = 0; g_din[i] = 0; g_cursor[i] = 0; }
}

__global__ void k_deg(const int* __restrict__ src, const int* __restrict__ dst, int E) {
    int e = blockIdx.x * blockDim.x + threadIdx.x;
    if (e < E) {
        atomicAdd(&g_dout[src[e]], 1);
        atomicAdd(&g_din [dst[e]], 1);
    }
}

// single-pass shuffle scan of g_din -> exclusive g_rs; also computes folded consts
__global__ void k_scan(const float* __restrict__ W0, const float* __restrict__ b0,
                       const float* __restrict__ W1) {
    __shared__ int wsum[32];
    __shared__ float sp[128], sn[128], sb[128];
    int t = threadIdx.x;                  // 1024
    int lane = t & 31, w = t >> 5;

    // ---- consts (threads 0..127, independent of scan data) ----
    if (t < 128) {
        float cp = 0.f, cn = 0.f, bm = 0.f;
        if (t < 100) {
            float w0 = W0[t], w1 = W1[t], p = w0 * w1;
            cp = p * (w0 > 0.f ? 1.f : 0.01f);
            cn = p * (w0 < 0.f ? 1.f : 0.01f);
            bm = fabsf(b0[t]);
        }
        sp[t] = cp; sn[t] = cn; sb[t] = bm;
    }

    // ---- scan: 16 elements per thread ----
    int base = t * 16;
    int v[16]; int s = 0;
    #pragma unroll
    for (int i = 0; i < 16; i++) {
        int idx = base + i;
        v[i] = (idx < NN) ? g_din[idx] : 0;
        s += v[i];
    }
    int incl = s;
    #pragma unroll
    for (int off = 1; off < 32; off <<= 1) {
        int n = __shfl_up_sync(0xffffffffu, incl, off);
        if (lane >= off) incl += n;
    }
    if (lane == 31) wsum[w] = incl;
    __syncthreads();
    if (w == 0) {
        int x = wsum[lane];
        #pragma unroll
        for (int off = 1; off < 32; off <<= 1) {
            int n = __shfl_up_sync(0xffffffffu, x, off);
            if (lane >= off) x += n;
        }
        wsum[lane] = x;                   // inclusive warp sums
    }
    // consts tree reduction in parallel with warp-0 work
    if (t < 64)  { sp[t] += sp[t + 64]; sn[t] += sn[t + 64]; sb[t] = fmaxf(sb[t], sb[t + 64]); }
    __syncthreads();
    int warpbase = (w == 0) ? 0 : wsum[w - 1];
    int run = warpbase + (incl - s);      // exclusive prefix for this thread
    #pragma unroll
    for (int i = 0; i < 16; i++) {
        int idx = base + i;
        if (idx <= NN) g_rs[idx] = run;   // idx==NN writes the total
        run += v[i];
    }
    if (t < 32) {
        float a = sp[t] + sp[t + 32], c = sn[t] + sn[t + 32];
        float m = fmaxf(sb[t], sb[t + 32]);
        #pragma unroll
        for (int off = 16; off; off >>= 1) {
            a += __shfl_down_sync(0xffffffffu, a, off);
            c += __shfl_down_sync(0xffffffffu, c, off);
            m = fmaxf(m, __shfl_down_sync(0xffffffffu, m, off));
        }
        if (t == 0) { g_consts[0] = a; g_consts[1] = c; g_consts[2] = m; }
    }
}

// CSR bucket fill + per-node inverse-sqrt degrees (independent work, same grid)
__global__ void k_fill(const int* __restrict__ src, const int* __restrict__ dst, int E) {
    int e = blockIdx.x * blockDim.x + threadIdx.x;
    if (e < NN) {
        g_rsdo[e] = rsqrtf(fmaxf((float)g_dout[e], 1.f));
        g_rsdi[e] = rsqrtf(fmaxf((float)g_din[e],  1.f));
    }
    if (e < E) {
        int d = dst[e];
        int p = atomicAdd(&g_cursor[d], 1);
        g_csr[g_rs[d] + p] = src[e];
    }
}

// ---------------- agg0 fused: gather(in_feat*rsdo[src]) -> s0 -> folded conv0/conv1 -> g_t ----
__global__ void k_agg0(const float* __restrict__ in_feat,
                       const float* __restrict__ W0, const float* __restrict__ b0,
                       const float* __restrict__ W1) {
    int node = blockIdx.x * (blockDim.x >> 5) + (threadIdx.x >> 5);
    if (node >= NN) return;
    int lane = threadIdx.x & 31;
    const float2* __restrict__ x = (const float2*)in_feat;
    int beg = g_rs[node], end = g_rs[node + 1];
    float ax = 0.f, ay = 0.f;
    #pragma unroll 4
    for (int i = beg; i < end; i++) {
        int s = __ldg(&g_csr[i]);
        float rs = __ldg(&g_rsdo[s]);          // warp-broadcast
        float2 v = x[s * 32 + lane];
        ax = fmaf(v.x, rs, ax); ay = fmaf(v.y, rs, ay);
    }
    float ri = g_rsdi[node];
    float s0x = ax * ri, s0y = ay * ri;
    float ro = g_rsdo[node];
    float tx, ty;
    if (g_consts[2] == 0.f) {                  // b0 == 0 fast path
        float cp = g_consts[0], cn = g_consts[1];
        tx = s0x * (s0x > 0.f ? cp : cn);
        ty = s0y * (s0y > 0.f ? cp : cn);
    } else {                                   // exact general fallback
        tx = 0.f; ty = 0.f;
        #pragma unroll 4
        for (int f = 0; f < 100; f++) {
            float w0 = __ldg(&W0[f]), bb = __ldg(&b0[f]), w1 = __ldg(&W1[f]);
            tx = fmaf(leaky(fmaf(s0x, w0, bb)), w1, tx);
            ty = fmaf(leaky(fmaf(s0y, w0, bb)), w1, ty);
        }
    }
    float2 o; o.x = tx * ro; o.y = ty * ro;
    ((float2*)g_t)[node * 32 + lane] = o;
}

// ---------------- agg1: gather g_t -> normalize + b1 + leaky -> g_z ----------------
__global__ void k_agg1(const float* __restrict__ b1) {
    int node = blockIdx.x * (blockDim.x >> 5) + (threadIdx.x >> 5);
    if (node >= NN) return;
    int lane = threadIdx.x & 31;
    const float2* __restrict__ x = (const float2*)g_t;
    int beg = g_rs[node], end = g_rs[node + 1];
    float ax = 0.f, ay = 0.f;
    #pragma unroll 4
    for (int i = beg; i < end; i++) {
        int s = __ldg(&g_csr[i]);
        float2 v = x[s * 32 + lane];
        ax += v.x; ay += v.y;
    }
    float r = g_rsdi[node];
    float bb = b1[0];
    float2 o;
    o.x = leaky(fmaf(ax, r, bb));
    o.y = leaky(fmaf(ay, r, bb));
    ((float2*)g_z)[node * 32 + lane] = o;
}

// ---------------- MLP layer 1: [64 x 15828] @ [15828 x 100], split-N partials ----------------
__global__ void k_mlp1(const float* __restrict__ lw0) {
    __shared__ float ws[100 * 64];
    __shared__ float zs[64 * 64];
    int blk = blockIdx.x;
    int n0 = blk * 64;
    int tid = threadIdx.x;   // 256
    for (int idx = tid; idx < 100 * 64; idx += 256) {
        int j = idx >> 6, i = idx & 63;
        int n = n0 + i;
        ws[idx] = (n < NN) ? lw0[j * NN + n] : 0.f;
    }
    for (int idx = tid; idx < 64 * 64; idx += 256) {
        int i = idx >> 6, b = idx & 63;
        int n = n0 + i;
        zs[idx] = (n < NN) ? g_z[n * 64 + b] : 0.f;
    }
    __syncthreads();
    int b = tid & 63, jg = tid >> 6;
    int jb = jg * 25;
    float acc[25];
    #pragma unroll
    for (int jj = 0; jj < 25; jj++) acc[jj] = 0.f;
    for (int i = 0; i < 64; i += 4) {
        float z0 = zs[(i + 0) * 64 + b];
        float z1 = zs[(i + 1) * 64 + b];
        float z2 = zs[(i + 2) * 64 + b];
        float z3 = zs[(i + 3) * 64 + b];
        #pragma unroll
        for (int jj = 0; jj < 25; jj++) {
            const float4 w = *(const float4*)&ws[(jb + jj) * 64 + i];
            acc[jj] = fmaf(z0, w.x, acc[jj]);
            acc[jj] = fmaf(z1, w.y, acc[jj]);
            acc[jj] = fmaf(z2, w.z, acc[jj]);
            acc[jj] = fmaf(z3, w.w, acc[jj]);
        }
    }
    #pragma unroll
    for (int jj = 0; jj < 25; jj++)
        g_partial[blk * 6400 + (jb + jj) * 64 + b] = acc[jj];
}

__global__ void k_mlp1_reduce(const float* __restrict__ lb0) {
    int idx = blockIdx.x * blockDim.x + threadIdx.x;
    if (idx >= 6400) return;
    int j = idx >> 6, b = idx & 63;
    float s = 0.f;
    for (int k = 0; k < NBLK_MLP1; k++) s += g_partial[k * 6400 + idx];
    s += lb0[j];
    g_y0[b * 100 + j] = leaky(s);
}

// ---------------- MLP layer 2: shared-staged, lanes-over-batch, broadcast weights ----------------
__global__ void k_tail_a(const float* __restrict__ lw2, const float* __restrict__ lb2) {
    __shared__ float y0s[100 * 65];           // [j*65 + b], pad kills bank conflicts
    int tid = threadIdx.x;                    // 1024
    for (int idx = tid; idx < 6400; idx += 1024) {
        int b = idx / 100, j = idx % 100;     // coalesced read of g_y0
        y0s[j * 65 + b] = g_y0[idx];
    }
    __syncthreads();
    int lane = tid & 31, w = tid >> 5;
    // 200 warp-tasks total, 50 per block (4 blocks)
    for (int tt = blockIdx.x * 50 + w; tt < blockIdx.x * 50 + 50; tt += 32) {
        int k = tt % 100, bh = tt / 100;
        int b = bh * 32 + lane;
        float acc = __ldg(&lb2[k]);
        #pragma unroll 4
        for (int j = 0; j < 100; j++)
            acc = fmaf(y0s[j * 65 + b], __ldg(&lw2[k * 100 + j]), acc);
        g_y1[k * 64 + b] = leaky(acc);        // coalesced over lanes
    }
}

// ---------------- MLP layer 3 ----------------
__global__ void k_tail_b(const float* __restrict__ lw3, const float* __restrict__ lb3,
                         float* __restrict__ out) {
    __shared__ float y1s[100 * 65];           // [k*65 + b]
    int tid = threadIdx.x;                    // 1024
    for (int idx = tid; idx < 6400; idx += 1024) {
        int k = idx >> 6, b = idx & 63;       // coalesced read of g_y1
        y1s[k * 65 + b] = g_y1[idx];
    }
    __syncthreads();
    int lane = tid & 31, w = tid >> 5;
    if (w < 20) {                             // 20 warp-tasks: (c, bhalf)
        int c = w % 10, bh = w / 10;
        int b = bh * 32 + lane;
        float acc = __ldg(&lb3[c]);
        #pragma unroll 4
        for (int k = 0; k < 100; k++)
            acc = fmaf(y1s[k * 65 + b], __ldg(&lw3[c * 100 + k]), acc);
        out[b * 10 + c] = leaky(acc);
    }
}

// ---------------- launch ----------------
extern "C" void kernel_launch(void* const* d_in, const int* in_sizes, int n_in,
                              void* d_out, int out_size) {
    const float* in_feat = (const float*)d_in[0];
    const int*   ei      = (const int*)  d_in[1];
    const float* W0      = (const float*)d_in[2];
    const float* b0      = (const float*)d_in[3];
    const float* W1      = (const float*)d_in[4];
    const float* b1      = (const float*)d_in[5];
    const float* lw0     = (const float*)d_in[6];
    const float* lb0     = (const float*)d_in[7];
    const float* lw2     = (const float*)d_in[8];
    const float* lb2     = (const float*)d_in[9];
    const float* lw3     = (const float*)d_in[10];
    const float* lb3     = (const float*)d_in[11];
    float* out = (float*)d_out;

    int E = in_sizes[1] / 2;
    const int* src = ei;
    const int* dst = ei + E;

    int gN   = (NN + 255) / 256;
    int gE   = (E + 255) / 256;
    int gAgg = (NN + 7) / 8;          // 8 warps (nodes) per 256-thread block

    k_init<<<gN, 256>>>();
    k_deg<<<gE, 256>>>(src, dst, E);
    k_scan<<<1, 1024>>>(W0, b0, W1);
    k_fill<<<gE, 256>>>(src, dst, E);
    k_agg0<<<gAgg, 256>>>(in_feat, W0, b0, W1);
    k_agg1<<<gAgg, 256>>>(b1);
    k_mlp1<<<NBLK_MLP1, 256>>>(lw0);
    k_mlp1_reduce<<<(6400 + 255) / 256, 256>>>(lb0);
    k_tail_a<<<4, 1024>>>(lw2, lb2);
    k_tail_b<<<1, 1024>>>(lw3, lb3, out);
}